// round 9
// baseline (speedup 1.0000x reference)
#include <cuda_runtime.h>
#include <stdint.h>

#define NB   256
#define NK   64
#define NL   32
#define NM   (NK * NL)            // 2048 rows per (side, batch) block
#define NTOT (2 * NB * NM)        // 1,048,576 output rows
#define SENT 32
#define TBL  4096
#define TMASK 4095u
#define EMPTYV 0xFFFFFFFFu
#define NODE_MASK 0x1FFFFu        // node ids < 100000 < 2^17

#define CTAS 592                  // 4 * 148 SMs: one co-resident wave
#define RPC  1772                 // ceil(NTOT / CTAS); slice spans <= 2 blocks
#define NTABS 512                 // one builder CTA per (side, batch) table

// first-seen tables (8 MB, L2-resident)
__device__ uint32_t g_tab[NTABS * TBL];
// resolved codes per row: own | cross<<6 | valid<<15  (2 MB, L2-resident)
__device__ uint16_t g_code[NTOT];
// monotonic epoch slots, +1 per slot per run -> replay-safe cross-slot compares
__device__ unsigned g_tab_ep[NTABS];
__device__ unsigned g_code_ep[CTAS];

__device__ __forceinline__ int ht_lookup_s(const uint32_t* __restrict__ tab, uint32_t node) {
    uint32_t h = (node * 2654435761u) & TMASK;
    #pragma unroll 1
    for (;;) {
        uint32_t cur = tab[h];
        if (cur == EMPTYV) return SENT;
        if ((cur & NODE_MASK) == node) return (int)(cur >> 17);
        h = (h + 1) & TMASK;
    }
}
__device__ __forceinline__ int ht_lookup_g(const uint32_t* __restrict__ tab, uint32_t node) {
    uint32_t h = (node * 2654435761u) & TMASK;
    #pragma unroll 1
    for (;;) {
        uint32_t cur = __ldg(&tab[h]);
        if (cur == EMPTYV) return SENT;
        if ((cur & NODE_MASK) == node) return (int)(cur >> 17);
        h = (h + 1) & TMASK;
    }
}

__global__ __launch_bounds__(512, 4) void wpe_kernel(
    const int* __restrict__ src_walks, const int* __restrict__ tgt_walks,
    const int* __restrict__ src_lens,  const int* __restrict__ tgt_lens,
    const float* __restrict__ own_emb, const float* __restrict__ cross_emb,
    float* __restrict__ out)
{
    __shared__ uint32_t tab[TBL];         // 16 KB (builders only)

    const int bid = blockIdx.x;
    const int tid = threadIdx.x;
    const int warp = tid >> 5, lane = tid & 31;
    const int half = lane >> 4, col = lane & 15;

    unsigned E = 0;                       // this run's epoch (learned at first publish)

    if (bid < NTABS) {
        // ── stage 1: build ONE (side,batch) table; dump to L2; publish ──
        const int s = bid >> 8, b = bid & (NB - 1);
        const int* w  = (s == 0 ? src_walks : tgt_walks) + b * NM;
        const int* ln = (s == 0 ? src_lens  : tgt_lens)  + b * NK;

        for (int i = tid; i < TBL; i += 512) tab[i] = EMPTYV;
        __syncthreads();

        #pragma unroll
        for (int r = 0; r < NM / 512; r++) {
            int m = tid + r * 512;
            int node = w[m];
            int l = m & (NL - 1);
            if (node != 0 && l < ln[m >> 5]) {
                uint32_t packed = ((uint32_t)l << 17) | (uint32_t)node;
                uint32_t h = ((uint32_t)node * 2654435761u) & TMASK;
                #pragma unroll 1
                for (;;) {
                    uint32_t cur = tab[h];
                    if (cur == EMPTYV) {
                        cur = atomicCAS(&tab[h], EMPTYV, packed);
                        if (cur == EMPTYV) break;
                    }
                    if ((cur & NODE_MASK) == (uint32_t)node) {
                        atomicMin(&tab[h], packed);   // same key: packed-min == pos-min
                        break;
                    }
                    h = (h + 1) & TMASK;
                }
            }
        }
        __syncthreads();

        {   // dump table for the partner builder
            uint4* dst = (uint4*)(g_tab + (size_t)bid * TBL);
            const uint4* srcv = (const uint4*)tab;
            #pragma unroll
            for (int i = tid; i < TBL / 4; i += 512) dst[i] = srcv[i];
        }
        __syncthreads();

        __shared__ unsigned sh_E;
        if (tid == 0) {
            __threadfence();                                  // publish g_tab dump
            sh_E = atomicAdd(&g_tab_ep[bid], 1u) + 1u;        // learn run epoch
            const int partner = bid ^ 256;                    // other side, same batch
            while (*(volatile unsigned*)&g_tab_ep[partner] < sh_E) __nanosleep(32);
            __threadfence();                                  // acquire partner table
        }
        __syncthreads();
        E = sh_E;

        // ── stage 2: resolve this block's 2048 codes (own: smem, cross: L2) ──
        const uint32_t* xtab = g_tab + (size_t)(bid ^ 256) * TBL;
        {
            // 4 consecutive rows per thread -> one 8-byte code store
            int m0 = tid * 4;
            uint16_t c[4];
            #pragma unroll
            for (int j = 0; j < 4; j++) {
                int m = m0 + j;
                int node = w[m];
                int l = m & (NL - 1);
                uint16_t p = 0;
                if (node != 0 && l < ln[m >> 5]) {
                    int own   = ht_lookup_s(tab,  (uint32_t)node);
                    int cross = ht_lookup_g(xtab, (uint32_t)node);
                    p = (uint16_t)(own | (cross << 6) | 0x8000);
                }
                c[j] = p;
            }
            uint2 pk;
            pk.x = (uint32_t)c[0] | ((uint32_t)c[1] << 16);
            pk.y = (uint32_t)c[2] | ((uint32_t)c[3] << 16);
            *(uint2*)(g_code + ((size_t)s * NB + b) * NM + m0) = pk;
        }
        __syncthreads();
        if (tid == 0) {
            __threadfence();                                  // publish codes
            atomicAdd(&g_code_ep[bid], 1u);
        }
    } else {
        // pure consumer: bump own slot to learn the run epoch
        __shared__ unsigned sh_E;
        if (tid == 0) sh_E = atomicAdd(&g_code_ep[bid], 1u) + 1u;
        __syncthreads();
        E = sh_E;
    }

    // ── stage 3: wait for the <=2 code blocks this slice touches, then emit ──
    long r0 = (long)bid * RPC;
    long r1 = r0 + RPC; if (r1 > NTOT) r1 = NTOT;
    const int cnt = (int)(r1 - r0);

    if (tid == 0) {
        const int blk0 = (int)(r0 >> 11);
        const int blk1 = (int)((r1 - 1) >> 11);
        while (*(volatile unsigned*)&g_code_ep[blk0] < E) __nanosleep(32);
        if (blk1 != blk0)
            while (*(volatile unsigned*)&g_code_ep[blk1] < E) __nanosleep(32);
        __threadfence();                                      // acquire codes
    }
    __syncthreads();

    const float4* oe = (const float4*)own_emb;     // 33 rows x 16 float4
    const float4* ce = (const float4*)cross_emb;
    float4* out4 = (float4*)out;

    int i = warp;
    for (; i + 64 <= cnt; i += 64) {               // 4-deep batches for store MLP
        uint32_t p[4]; float4 v[4];
        #pragma unroll
        for (int j = 0; j < 4; j++) p[j] = __ldg(&g_code[r0 + i + j * 16]);
        #pragma unroll
        for (int j = 0; j < 4; j++) {
            v[j] = make_float4(0.f, 0.f, 0.f, 0.f);
            if (p[j] & 0x8000u) {
                int own   = p[j] & 63;
                int cross = (p[j] >> 6) & 63;
                v[j] = half ? __ldg(&ce[cross * 16 + col])
                            : __ldg(&oe[own   * 16 + col]);
            }
        }
        #pragma unroll
        for (int j = 0; j < 4; j++)
            __stcs(&out4[(size_t)(r0 + i + j * 16) * 32 + lane], v[j]);
    }
    for (; i < cnt; i += 16) {                     // remainder
        uint32_t p = __ldg(&g_code[r0 + i]);
        float4 v = make_float4(0.f, 0.f, 0.f, 0.f);
        if (p & 0x8000u) {
            int own   = p & 63;
            int cross = (p >> 6) & 63;
            v = half ? __ldg(&ce[cross * 16 + col])
                     : __ldg(&oe[own   * 16 + col]);
        }
        __stcs(&out4[(size_t)(r0 + i) * 32 + lane], v);
    }
}

extern "C" void kernel_launch(void* const* d_in, const int* in_sizes, int n_in,
                              void* d_out, int out_size) {
    (void)in_sizes; (void)n_in; (void)out_size;
    wpe_kernel<<<CTAS, 512>>>(
        (const int*)d_in[0], (const int*)d_in[1],
        (const int*)d_in[2], (const int*)d_in[3],
        (const float*)d_in[4], (const float*)d_in[5],
        (float*)d_out);
}

// round 10
// speedup vs baseline: 1.0474x; 1.0474x over previous
#include <cuda_runtime.h>
#include <stdint.h>

#define NB   256
#define NK   64
#define NL   32
#define NM   (NK * NL)            // 2048 rows per (side, batch) block
#define NTOT (2 * NB * NM)        // 1,048,576 output rows
#define SENT 32
#define TBL  4096
#define TMASK 4095u
#define EMPTYV 0xFFFFFFFFu
#define NODE_MASK 0x1FFFFu        // node ids < 100000 < 2^17
#define VALIDF 0x80000000u

#define CTAS 592                  // 4 * 148 SMs: one co-resident wave
#define RPC  1772                 // ceil(NTOT / CTAS); slice spans <= 2 blocks
#define NTABS 512                 // one builder CTA per (side, batch) table

// first-seen tables (8 MB, L2-resident)
__device__ uint32_t g_tab[NTABS * TBL];
// monotonic per-CTA epoch slots: +1 per slot per run -> replay-safe
__device__ unsigned g_ready[CTAS];

__device__ __forceinline__ int ht_lookup_g(const uint32_t* __restrict__ tab, uint32_t node) {
    uint32_t h = (node * 2654435761u) & TMASK;
    #pragma unroll 1
    for (;;) {
        uint32_t cur = __ldg(&tab[h]);
        if (cur == EMPTYV) return SENT;
        if ((cur & NODE_MASK) == node) return (int)(cur >> 17);
        h = (h + 1) & TMASK;
    }
}

__global__ __launch_bounds__(512, 4) void wpe_kernel(
    const int* __restrict__ src_walks, const int* __restrict__ tgt_walks,
    const int* __restrict__ src_lens,  const int* __restrict__ tgt_lens,
    const float* __restrict__ own_emb, const float* __restrict__ cross_emb,
    float* __restrict__ out)
{
    __shared__ uint32_t tab[TBL];         // 16 KB (builders only)
    __shared__ uint32_t s_info[RPC + 4];  // 7 KB: node|valid -> later code

    const int bid = blockIdx.x;
    const int tid = threadIdx.x;
    const int warp = tid >> 5, lane = tid & 31;
    const int half = lane >> 4, col = lane & 15;

    long r0 = (long)bid * RPC;
    long r1 = r0 + RPC; if (r1 > NTOT) r1 = NTOT;
    const int cnt = (int)(r1 - r0);

    __shared__ unsigned sh_E;

    // ── stage 1: builders make ONE (side,batch) table, dump, publish ASAP ──
    if (bid < NTABS) {
        const int s = bid >> 8, b = bid & (NB - 1);
        const int* w  = (s == 0 ? src_walks : tgt_walks) + b * NM;
        const int* ln = (s == 0 ? src_lens  : tgt_lens)  + b * NK;

        for (int i = tid; i < TBL; i += 512) tab[i] = EMPTYV;
        __syncthreads();

        #pragma unroll
        for (int r = 0; r < NM / 512; r++) {
            int m = tid + r * 512;
            int node = w[m];
            int l = m & (NL - 1);
            if (node != 0 && l < ln[m >> 5]) {
                uint32_t packed = ((uint32_t)l << 17) | (uint32_t)node;
                uint32_t h = ((uint32_t)node * 2654435761u) & TMASK;
                #pragma unroll 1
                for (;;) {
                    uint32_t cur = tab[h];
                    if (cur == EMPTYV) {
                        cur = atomicCAS(&tab[h], EMPTYV, packed);
                        if (cur == EMPTYV) break;
                    }
                    if ((cur & NODE_MASK) == (uint32_t)node) {
                        atomicMin(&tab[h], packed);   // same key: packed-min == pos-min
                        break;
                    }
                    h = (h + 1) & TMASK;
                }
            }
        }
        __syncthreads();

        uint4* dst = (uint4*)(g_tab + (size_t)bid * TBL);
        const uint4* srcv = (const uint4*)tab;
        #pragma unroll
        for (int i = tid; i < TBL / 4; i += 512) dst[i] = srcv[i];
        __syncthreads();
        if (tid == 0) {
            __threadfence();                               // publish table
            sh_E = atomicAdd(&g_ready[bid], 1u) + 1u;      // learn run epoch
        }
    } else {
        if (tid == 0) sh_E = atomicAdd(&g_ready[bid], 1u) + 1u;
    }

    // ── stage 2: validity prepass (no tables needed) ──
    for (int i = tid; i < cnt; i += 512) {
        long r = r0 + i;
        const int s = (int)(r >> 19);
        const int b = (int)((r >> 11) & (NB - 1));
        const int m = (int)(r & (NM - 1));
        const int* w  = (s == 0 ? src_walks : tgt_walks) + b * NM;
        const int* ln = (s == 0 ? src_lens  : tgt_lens)  + b * NK;
        int node = w[m];
        int l = m & (NL - 1);
        s_info[i] = (node != 0 && l < ln[m >> 5]) ? ((uint32_t)node | VALIDF) : 0u;
    }
    __syncthreads();
    const unsigned E = sh_E;

    // ── stage 3: emit zeros for invalid rows NOW (overlaps builder latency) ──
    float4* out4 = (float4*)out;
    const float4 z4 = make_float4(0.f, 0.f, 0.f, 0.f);
    for (int i = warp; i < cnt; i += 16)
        if (!(s_info[i] & VALIDF))
            __stcs(&out4[(size_t)(r0 + i) * 32 + lane], z4);

    // ── stage 4: wait for the <=2 batches' tables (usually already done) ──
    if (tid == 0) {
        const int b0 = (int)((r0 >> 11) & (NB - 1));
        const int b1 = (int)(((r1 - 1) >> 11) & (NB - 1));
        while (*(volatile unsigned*)&g_ready[b0]       < E) __nanosleep(32);
        while (*(volatile unsigned*)&g_ready[256 + b0] < E) __nanosleep(32);
        if (b1 != b0) {
            while (*(volatile unsigned*)&g_ready[b1]       < E) __nanosleep(32);
            while (*(volatile unsigned*)&g_ready[256 + b1] < E) __nanosleep(32);
        }
        __threadfence();                                   // acquire tables
    }
    __syncthreads();

    // ── stage 5: resolve valid rows from L2 tables ──
    for (int i = tid; i < cnt; i += 512) {
        uint32_t info = s_info[i];
        if (info & VALIDF) {
            long r = r0 + i;
            const int s = (int)(r >> 19);
            const int b = (int)((r >> 11) & (NB - 1));
            uint32_t node = info & NODE_MASK;
            const uint32_t* mytab = g_tab + ((size_t)(s       * NB + b)) * TBL;
            const uint32_t* xtab  = g_tab + ((size_t)((s ^ 1) * NB + b)) * TBL;
            int own   = ht_lookup_g(mytab, node);
            int cross = ht_lookup_g(xtab,  node);
            s_info[i] = (uint32_t)(own | (cross << 6)) | VALIDF;
        }
    }
    __syncthreads();

    // ── stage 6: emit valid rows (4-deep batching for store MLP) ──
    const float4* oe = (const float4*)own_emb;     // 33 rows x 16 float4
    const float4* ce = (const float4*)cross_emb;

    int i = warp;
    for (; i + 64 <= cnt; i += 64) {
        uint32_t p[4];
        #pragma unroll
        for (int j = 0; j < 4; j++) p[j] = s_info[i + j * 16];
        #pragma unroll
        for (int j = 0; j < 4; j++) {
            if (p[j] & VALIDF) {
                int own   = p[j] & 63;
                int cross = (p[j] >> 6) & 63;
                float4 v = half ? __ldg(&ce[cross * 16 + col])
                                : __ldg(&oe[own   * 16 + col]);
                __stcs(&out4[(size_t)(r0 + i + j * 16) * 32 + lane], v);
            }
        }
    }
    for (; i < cnt; i += 16) {
        uint32_t p = s_info[i];
        if (p & VALIDF) {
            int own   = p & 63;
            int cross = (p >> 6) & 63;
            float4 v = half ? __ldg(&ce[cross * 16 + col])
                            : __ldg(&oe[own   * 16 + col]);
            __stcs(&out4[(size_t)(r0 + i) * 32 + lane], v);
        }
    }
}

extern "C" void kernel_launch(void* const* d_in, const int* in_sizes, int n_in,
                              void* d_out, int out_size) {
    (void)in_sizes; (void)n_in; (void)out_size;
    wpe_kernel<<<CTAS, 512>>>(
        (const int*)d_in[0], (const int*)d_in[1],
        (const int*)d_in[2], (const int*)d_in[3],
        (const float*)d_in[4], (const float*)d_in[5],
        (float*)d_out);
}